// round 2
// baseline (speedup 1.0000x reference)
#include <cuda_runtime.h>
#include <math.h>

// Problem constants
#define XD 8            // feature dims (XD == ZD == 8)
#define LCH 32          // t-chunk length
#define NCMAX 128       // max number of chunks

// Scratch: per-chunk scan summaries U[c][r] and prefix carries C[c][r]
__device__ float g_U[NCMAX * 8192];
__device__ float g_C[NCMAX * 8192];

// ---------------- packed fp32x2 helpers (sm_100a) ----------------
static __device__ __forceinline__ float2 ffma2(float2 a, float2 b, float2 c) {
    float2 d;
    asm("{\n\t"
        ".reg .b64 ra, rb, rc, rd;\n\t"
        "mov.b64 ra, {%2, %3};\n\t"
        "mov.b64 rb, {%4, %5};\n\t"
        "mov.b64 rc, {%6, %7};\n\t"
        "fma.rn.f32x2 rd, ra, rb, rc;\n\t"
        "mov.b64 {%0, %1}, rd;\n\t"
        "}"
        : "=f"(d.x), "=f"(d.y)
        : "f"(a.x), "f"(a.y), "f"(b.x), "f"(b.y), "f"(c.x), "f"(c.y));
    return d;
}

static __device__ __forceinline__ float2 fmul2(float2 a, float2 b) {
    float2 d;
    asm("{\n\t"
        ".reg .b64 ra, rb, rd;\n\t"
        "mov.b64 ra, {%2, %3};\n\t"
        "mov.b64 rb, {%4, %5};\n\t"
        "mul.rn.f32x2 rd, ra, rb;\n\t"
        "mov.b64 {%0, %1}, rd;\n\t"
        "}"
        : "=f"(d.x), "=f"(d.y)
        : "f"(a.x), "f"(a.y), "f"(b.x), "f"(b.y));
    return d;
}

static __device__ __forceinline__ float2 fadd2(float2 a, float2 b) {
    float2 d;
    asm("{\n\t"
        ".reg .b64 ra, rb, rd;\n\t"
        "mov.b64 ra, {%2, %3};\n\t"
        "mov.b64 rb, {%4, %5};\n\t"
        "add.rn.f32x2 rd, ra, rb;\n\t"
        "mov.b64 {%0, %1}, rd;\n\t"
        "}"
        : "=f"(d.x), "=f"(d.y)
        : "f"(a.x), "f"(a.y), "f"(b.x), "f"(b.y));
    return d;
}

static __device__ __forceinline__ float2 splat(float v) { return make_float2(v, v); }

static __device__ __forceinline__ float sigmoidf_(float x) {
    return 1.0f / (1.0f + expf(-x));
}

// Load coefficient row-pair {rA, rB} packed into float2[8]
static __device__ __forceinline__ void load_pair(const float* __restrict__ base,
                                                 int rA, int rB, float2 o[XD]) {
    const float4 a0 = *(const float4*)(base + rA * XD);
    const float4 a1 = *(const float4*)(base + rA * XD + 4);
    const float4 b0 = *(const float4*)(base + rB * XD);
    const float4 b1 = *(const float4*)(base + rB * XD + 4);
    o[0] = make_float2(a0.x, b0.x); o[1] = make_float2(a0.y, b0.y);
    o[2] = make_float2(a0.z, b0.z); o[3] = make_float2(a0.w, b0.w);
    o[4] = make_float2(a1.x, b1.x); o[5] = make_float2(a1.y, b1.y);
    o[6] = make_float2(a1.z, b1.z); o[7] = make_float2(a1.w, b1.w);
}

// b_t for a row-pair: gamma . Z[t], two 4-chains for shorter latency path
static __device__ __forceinline__ float2 compute_b(const float2 ga[XD],
                                                   float4 z0, float4 z1) {
    float2 b0 = fmul2(ga[0], splat(z0.x));
    b0 = ffma2(ga[1], splat(z0.y), b0);
    b0 = ffma2(ga[2], splat(z0.z), b0);
    b0 = ffma2(ga[3], splat(z0.w), b0);
    float2 b1 = fmul2(ga[4], splat(z1.x));
    b1 = ffma2(ga[5], splat(z1.y), b1);
    b1 = ffma2(ga[6], splat(z1.z), b1);
    b1 = ffma2(ga[7], splat(z1.w), b1);
    return fadd2(b0, b1);
}

// ---------------- Kernel 1: per-chunk scan summaries ----------------
// U[c][r] = sum_{s in chunk c} Ghat^{(chunk_end-1-s)} * b_s
__global__ __launch_bounds__(128) void dlm_chunk_kernel(
    const float* __restrict__ Z, const float* __restrict__ G,
    const float* __restrict__ gamma, int R, int T)
{
    __shared__ __align__(16) float sZ[LCH * XD];
    const int c = blockIdx.y;
    const int t0 = c * LCH;
    for (int i = threadIdx.x; i < LCH * XD; i += blockDim.x)
        sZ[i] = Z[t0 * XD + i];
    __syncthreads();

    const int warp = threadIdx.x >> 5, lane = threadIdx.x & 31;
    const int rbase = blockIdx.x * 256 + warp * 64;
    const int rA = rbase + lane, rB = rA + 32;

    float2 ga[XD];
    load_pair(gamma, rA, rB, ga);
    const float2 g2 = make_float2(sigmoidf_(G[rA]), sigmoidf_(G[rB]));

    float2 u = make_float2(0.f, 0.f);
#pragma unroll 4
    for (int i = 0; i < LCH; ++i) {
        const float4 z0 = *(const float4*)&sZ[i * XD];
        const float4 z1 = *(const float4*)&sZ[i * XD + 4];
        const float2 b = compute_b(ga, z0, z1);
        u = ffma2(g2, u, b);
    }
    g_U[c * R + rA] = u.x;
    g_U[c * R + rB] = u.y;
}

// ---------------- Kernel 1b: serial prefix over chunk summaries ----------------
// C[c][r] = theta at t = c*LCH  (carry-in for chunk c)
// C[0]=0; C[c] = Ghat^LCH * C[c-1] + U[c-1]
__global__ __launch_bounds__(256) void dlm_carry_kernel(
    const float* __restrict__ G, int R, int NC)
{
    const int r = blockIdx.x * blockDim.x + threadIdx.x;
    if (r >= R) return;
    float g = sigmoidf_(G[r]);
    float gl = g;
#pragma unroll
    for (int s = 0; s < 5; ++s) gl = gl * gl;   // Ghat^32 (LCH=32=2^5)

    float th = 0.f;
#pragma unroll 4
    for (int c = 0; c < NC; ++c) {
        g_C[c * R + r] = th;
        th = fmaf(gl, th, g_U[c * R + r]);
    }
}

// ---------------- Kernel 2: main compute ----------------
// out[r,t] = theta[r,t] + eta[r].X[t] + zeta[r].Z[t]
// 64-thread CTAs (2 warps), each warp owns 64 rows x 32 t.
__global__ __launch_bounds__(64) void dlm_main_kernel(
    const float* __restrict__ X, const float* __restrict__ Z,
    const float* __restrict__ G, const float* __restrict__ eta,
    const float* __restrict__ zeta, const float* __restrict__ gamma,
    float* __restrict__ out, int R, int T)
{
    __shared__ __align__(16) float sX[LCH * XD];
    __shared__ __align__(16) float sZ[LCH * XD];
    __shared__ float tile[2][32 * 65];   // per warp: [t (stride 65)][row 0..63]

    const int c = blockIdx.y;
    const int t0 = c * LCH;
    for (int i = threadIdx.x; i < LCH * XD; i += blockDim.x) {
        sX[i] = X[t0 * XD + i];
        sZ[i] = Z[t0 * XD + i];
    }
    __syncthreads();

    const int warp = threadIdx.x >> 5, lane = threadIdx.x & 31;
    const int rbase = blockIdx.x * 128 + warp * 64;
    const int rA = rbase + lane, rB = rA + 32;

    float2 et[XD], ze[XD], ga[XD];
    load_pair(eta,   rA, rB, et);
    load_pair(zeta,  rA, rB, ze);
    load_pair(gamma, rA, rB, ga);
    const float2 g2 = make_float2(sigmoidf_(G[rA]), sigmoidf_(G[rB]));

    // Single carry load — prefix already computed by dlm_carry_kernel
    float2 th = make_float2(__ldg(&g_C[c * R + rA]), __ldg(&g_C[c * R + rB]));

    float* mytile = tile[warp];
#pragma unroll 4
    for (int i = 0; i < LCH; ++i) {
        const float4 x0 = *(const float4*)&sX[i * XD];
        const float4 x1 = *(const float4*)&sX[i * XD + 4];
        const float4 z0 = *(const float4*)&sZ[i * XD];
        const float4 z1 = *(const float4*)&sZ[i * XD + 4];

        // Two independent chains (depth ~9 instead of 17) + b in parallel
        float2 accA = th;
        accA = ffma2(et[0], splat(x0.x), accA);
        accA = ffma2(et[1], splat(x0.y), accA);
        accA = ffma2(et[2], splat(x0.z), accA);
        accA = ffma2(et[3], splat(x0.w), accA);
        accA = ffma2(et[4], splat(x1.x), accA);
        accA = ffma2(et[5], splat(x1.y), accA);
        accA = ffma2(et[6], splat(x1.z), accA);
        accA = ffma2(et[7], splat(x1.w), accA);

        float2 accB = fmul2(ze[0], splat(z0.x));
        accB = ffma2(ze[1], splat(z0.y), accB);
        accB = ffma2(ze[2], splat(z0.z), accB);
        accB = ffma2(ze[3], splat(z0.w), accB);
        accB = ffma2(ze[4], splat(z1.x), accB);
        accB = ffma2(ze[5], splat(z1.y), accB);
        accB = ffma2(ze[6], splat(z1.z), accB);
        accB = ffma2(ze[7], splat(z1.w), accB);

        const float2 b = compute_b(ga, z0, z1);
        const float2 acc = fadd2(accA, accB);
        th = ffma2(g2, th, b);           // theta_{t+1} = Ghat*theta_t + b_t

        mytile[i * 65 + lane]      = acc.x;
        mytile[i * 65 + lane + 32] = acc.y;
    }
    __syncwarp();

    // Coalesced writeback: 16 x STG.128, transpose reads conflict-free
    // (banks 4*tg + row + j cover 0..31 exactly once per LDS instruction)
#pragma unroll
    for (int k = 0; k < 16; ++k) {
        const int sid = k * 32 + lane;
        const int row = sid >> 3;          // 0..63
        const int tg  = (sid & 7) << 2;    // 0,4,...,28
        float4 v;
        v.x = mytile[(tg + 0) * 65 + row];
        v.y = mytile[(tg + 1) * 65 + row];
        v.z = mytile[(tg + 2) * 65 + row];
        v.w = mytile[(tg + 3) * 65 + row];
        *(float4*)&out[(rbase + row) * T + t0 + tg] = v;
    }
}

// ---------------- launch ----------------
extern "C" void kernel_launch(void* const* d_in, const int* in_sizes, int n_in,
                              void* d_out, int out_size) {
    const float* X     = (const float*)d_in[0];   // [T, 8]
    const float* Z     = (const float*)d_in[1];   // [T, 8]
    const float* G     = (const float*)d_in[2];   // [R]
    const float* eta   = (const float*)d_in[3];   // [R, 8]
    const float* zeta  = (const float*)d_in[4];   // [R, 8]
    const float* gamma = (const float*)d_in[5];   // [R, 8]
    float* out = (float*)d_out;                   // [R, T]

    const int T = in_sizes[0] / XD;   // 2048
    const int R = in_sizes[2];        // 4096
    const int NC = T / LCH;           // 64 chunks

    // K1: chunk summaries. grid (R/256, NC), 128 threads
    dlm_chunk_kernel<<<dim3(R / 256, NC), 128>>>(Z, G, gamma, R, T);
    // K1b: serial prefix over chunks, 1 thread per row
    dlm_carry_kernel<<<(R + 255) / 256, 256>>>(G, R, NC);
    // K2: main. grid (R/128, NC), 64 threads (2 warps)
    dlm_main_kernel<<<dim3(R / 128, NC), 64>>>(X, Z, G, eta, zeta, gamma, out, R, T);
}

// round 3
// speedup vs baseline: 1.2626x; 1.2626x over previous
#include <cuda_runtime.h>
#include <math.h>

// Problem constants
#define XD 8            // feature dims (XD == ZD == 8)
#define LCH 32          // t-chunk length

// Scratch: per-chunk scan summaries U[c][r]
__device__ float g_U[64 * 8192];

// ---------------- packed fp32x2 helpers (sm_100a) ----------------
static __device__ __forceinline__ float2 ffma2(float2 a, float2 b, float2 c) {
    float2 d;
    asm("{\n\t"
        ".reg .b64 ra, rb, rc, rd;\n\t"
        "mov.b64 ra, {%2, %3};\n\t"
        "mov.b64 rb, {%4, %5};\n\t"
        "mov.b64 rc, {%6, %7};\n\t"
        "fma.rn.f32x2 rd, ra, rb, rc;\n\t"
        "mov.b64 {%0, %1}, rd;\n\t"
        "}"
        : "=f"(d.x), "=f"(d.y)
        : "f"(a.x), "f"(a.y), "f"(b.x), "f"(b.y), "f"(c.x), "f"(c.y));
    return d;
}

static __device__ __forceinline__ float2 fmul2(float2 a, float2 b) {
    float2 d;
    asm("{\n\t"
        ".reg .b64 ra, rb, rd;\n\t"
        "mov.b64 ra, {%2, %3};\n\t"
        "mov.b64 rb, {%4, %5};\n\t"
        "mul.rn.f32x2 rd, ra, rb;\n\t"
        "mov.b64 {%0, %1}, rd;\n\t"
        "}"
        : "=f"(d.x), "=f"(d.y)
        : "f"(a.x), "f"(a.y), "f"(b.x), "f"(b.y));
    return d;
}

static __device__ __forceinline__ float2 fadd2(float2 a, float2 b) {
    float2 d;
    asm("{\n\t"
        ".reg .b64 ra, rb, rd;\n\t"
        "mov.b64 ra, {%2, %3};\n\t"
        "mov.b64 rb, {%4, %5};\n\t"
        "add.rn.f32x2 rd, ra, rb;\n\t"
        "mov.b64 {%0, %1}, rd;\n\t"
        "}"
        : "=f"(d.x), "=f"(d.y)
        : "f"(a.x), "f"(a.y), "f"(b.x), "f"(b.y));
    return d;
}

static __device__ __forceinline__ float2 splat(float v) { return make_float2(v, v); }

static __device__ __forceinline__ float sigmoidf_(float x) {
    return 1.0f / (1.0f + expf(-x));
}

// Load coefficient row-pair {rA, rB} packed into float2[8]
static __device__ __forceinline__ void load_pair(const float* __restrict__ base,
                                                 int rA, int rB, float2 o[XD]) {
    const float4 a0 = *(const float4*)(base + rA * XD);
    const float4 a1 = *(const float4*)(base + rA * XD + 4);
    const float4 b0 = *(const float4*)(base + rB * XD);
    const float4 b1 = *(const float4*)(base + rB * XD + 4);
    o[0] = make_float2(a0.x, b0.x); o[1] = make_float2(a0.y, b0.y);
    o[2] = make_float2(a0.z, b0.z); o[3] = make_float2(a0.w, b0.w);
    o[4] = make_float2(a1.x, b1.x); o[5] = make_float2(a1.y, b1.y);
    o[6] = make_float2(a1.z, b1.z); o[7] = make_float2(a1.w, b1.w);
}

// b_t for a row-pair: gamma . Z[t], two 4-chains for shorter latency path
static __device__ __forceinline__ float2 compute_b(const float2 ga[XD],
                                                   float4 z0, float4 z1) {
    float2 b0 = fmul2(ga[0], splat(z0.x));
    b0 = ffma2(ga[1], splat(z0.y), b0);
    b0 = ffma2(ga[2], splat(z0.z), b0);
    b0 = ffma2(ga[3], splat(z0.w), b0);
    float2 b1 = fmul2(ga[4], splat(z1.x));
    b1 = ffma2(ga[5], splat(z1.y), b1);
    b1 = ffma2(ga[6], splat(z1.z), b1);
    b1 = ffma2(ga[7], splat(z1.w), b1);
    return fadd2(b0, b1);
}

// ---------------- Kernel 1: per-chunk scan summaries ----------------
// U[c][r] = sum_{s in chunk c} Ghat^{(chunk_end-1-s)} * b_s
// 4 rows per lane (two independent f32x2 recurrences) for ILP.
__global__ __launch_bounds__(128) void dlm_chunk_kernel(
    const float* __restrict__ Z, const float* __restrict__ G,
    const float* __restrict__ gamma, int R)
{
    __shared__ __align__(16) float sZ[LCH * XD];
    const int c = blockIdx.y;
    const int t0 = c * LCH;
    for (int i = threadIdx.x; i < LCH * XD; i += blockDim.x)
        sZ[i] = Z[t0 * XD + i];
    __syncthreads();

    const int warp = threadIdx.x >> 5, lane = threadIdx.x & 31;
    const int rbase = blockIdx.x * 512 + warp * 128;
    const int rA = rbase + lane;          // rows rA, rA+32, rA+64, rA+96

    float2 ga0[XD], ga1[XD];
    load_pair(gamma, rA,      rA + 32, ga0);
    load_pair(gamma, rA + 64, rA + 96, ga1);
    const float2 g20 = make_float2(sigmoidf_(G[rA]),      sigmoidf_(G[rA + 32]));
    const float2 g21 = make_float2(sigmoidf_(G[rA + 64]), sigmoidf_(G[rA + 96]));

    float2 u0 = make_float2(0.f, 0.f);
    float2 u1 = make_float2(0.f, 0.f);
#pragma unroll 8
    for (int i = 0; i < LCH; ++i) {
        const float4 z0 = *(const float4*)&sZ[i * XD];
        const float4 z1 = *(const float4*)&sZ[i * XD + 4];
        const float2 b0 = compute_b(ga0, z0, z1);
        const float2 b1 = compute_b(ga1, z0, z1);
        u0 = ffma2(g20, u0, b0);
        u1 = ffma2(g21, u1, b1);
    }
    g_U[c * R + rA]      = u0.x;
    g_U[c * R + rA + 32] = u0.y;
    g_U[c * R + rA + 64] = u1.x;
    g_U[c * R + rA + 96] = u1.y;
}

// ---------------- Kernel 2: main compute ----------------
// out[r,t] = theta[r,t] + eta[r].X[t] + zeta[r].Z[t]
// 128-thread CTAs (4 warps), each warp owns 64 rows x 32 t.
// Carry-in rebuilt from g_U by a per-CTA prefix scan.
__global__ __launch_bounds__(128) void dlm_main_kernel(
    const float* __restrict__ X, const float* __restrict__ Z,
    const float* __restrict__ G, const float* __restrict__ eta,
    const float* __restrict__ zeta, const float* __restrict__ gamma,
    float* __restrict__ out, int R, int T)
{
    __shared__ __align__(16) float sX[LCH * XD];
    __shared__ __align__(16) float sZ[LCH * XD];
    __shared__ float tile[4][32 * 65];   // per warp: [t (stride 65)][row 0..63]

    const int c = blockIdx.y;
    const int t0 = c * LCH;
    for (int i = threadIdx.x; i < LCH * XD; i += blockDim.x) {
        sX[i] = X[t0 * XD + i];
        sZ[i] = Z[t0 * XD + i];
    }
    __syncthreads();

    const int warp = threadIdx.x >> 5, lane = threadIdx.x & 31;
    const int rbase = blockIdx.x * 256 + warp * 64;
    const int rA = rbase + lane, rB = rA + 32;

    float2 et[XD], ze[XD], ga[XD];
    load_pair(eta,   rA, rB, et);
    load_pair(zeta,  rA, rB, ze);
    load_pair(gamma, rA, rB, ga);
    const float2 g2 = make_float2(sigmoidf_(G[rA]), sigmoidf_(G[rB]));

    // Ghat^LCH via exact repeated squaring (LCH = 32 = 2^5)
    float2 gl = g2;
#pragma unroll
    for (int s = 0; s < 5; ++s) gl = fmul2(gl, gl);

    // Carry-in: theta at t0 = scan over previous chunks' U (loads pipeline, chain is 4cyc/step)
    float2 th = make_float2(0.f, 0.f);
#pragma unroll 4
    for (int j = 0; j < c; ++j) {
        const float2 u = make_float2(__ldg(&g_U[j * R + rA]),
                                     __ldg(&g_U[j * R + rB]));
        th = ffma2(gl, th, u);
    }

    float* mytile = tile[warp];
#pragma unroll 8
    for (int i = 0; i < LCH; ++i) {
        const float4 x0 = *(const float4*)&sX[i * XD];
        const float4 x1 = *(const float4*)&sX[i * XD + 4];
        const float4 z0 = *(const float4*)&sZ[i * XD];
        const float4 z1 = *(const float4*)&sZ[i * XD + 4];

        // Two independent chains (depth ~9) + b chain in parallel
        float2 accA = th;
        accA = ffma2(et[0], splat(x0.x), accA);
        accA = ffma2(et[1], splat(x0.y), accA);
        accA = ffma2(et[2], splat(x0.z), accA);
        accA = ffma2(et[3], splat(x0.w), accA);
        accA = ffma2(et[4], splat(x1.x), accA);
        accA = ffma2(et[5], splat(x1.y), accA);
        accA = ffma2(et[6], splat(x1.z), accA);
        accA = ffma2(et[7], splat(x1.w), accA);

        float2 accB = fmul2(ze[0], splat(z0.x));
        accB = ffma2(ze[1], splat(z0.y), accB);
        accB = ffma2(ze[2], splat(z0.z), accB);
        accB = ffma2(ze[3], splat(z0.w), accB);
        accB = ffma2(ze[4], splat(z1.x), accB);
        accB = ffma2(ze[5], splat(z1.y), accB);
        accB = ffma2(ze[6], splat(z1.z), accB);
        accB = ffma2(ze[7], splat(z1.w), accB);

        const float2 b = compute_b(ga, z0, z1);
        const float2 acc = fadd2(accA, accB);
        th = ffma2(g2, th, b);           // theta_{t+1} = Ghat*theta_t + b_t

        mytile[i * 65 + lane]      = acc.x;
        mytile[i * 65 + lane + 32] = acc.y;
    }
    __syncwarp();

    // Coalesced writeback: 16 x STG.128 per thread-iter; transpose reads are
    // conflict-free (65 ≡ 1 mod 32 → bank = (tg + j + row) % 32, bijective per LDS)
#pragma unroll
    for (int k = 0; k < 16; ++k) {
        const int sid = k * 32 + lane;
        const int row = sid >> 3;          // 0..63
        const int tg  = (sid & 7) << 2;    // 0,4,...,28
        float4 v;
        v.x = mytile[(tg + 0) * 65 + row];
        v.y = mytile[(tg + 1) * 65 + row];
        v.z = mytile[(tg + 2) * 65 + row];
        v.w = mytile[(tg + 3) * 65 + row];
        *(float4*)&out[(rbase + row) * T + t0 + tg] = v;
    }
}

// ---------------- launch ----------------
extern "C" void kernel_launch(void* const* d_in, const int* in_sizes, int n_in,
                              void* d_out, int out_size) {
    const float* X     = (const float*)d_in[0];   // [T, 8]
    const float* Z     = (const float*)d_in[1];   // [T, 8]
    const float* G     = (const float*)d_in[2];   // [R]
    const float* eta   = (const float*)d_in[3];   // [R, 8]
    const float* zeta  = (const float*)d_in[4];   // [R, 8]
    const float* gamma = (const float*)d_in[5];   // [R, 8]
    float* out = (float*)d_out;                   // [R, T]

    const int T = in_sizes[0] / XD;   // 2048
    const int R = in_sizes[2];        // 4096
    const int NC = T / LCH;           // 64 chunks

    // K1: chunk summaries for chunks 0..NC-2 (U of last chunk is never read).
    // grid (R/512, NC-1), 128 threads, 4 rows per lane.
    dlm_chunk_kernel<<<dim3(R / 512, NC - 1), 128>>>(Z, G, gamma, R);
    // K2: main. grid (R/256, NC), 128 threads (4 warps x 64 rows).
    dlm_main_kernel<<<dim3(R / 256, NC), 128>>>(X, Z, G, eta, zeta, gamma, out, R, T);
}